// round 1
// baseline (speedup 1.0000x reference)
#include <cuda_runtime.h>
#include <math_constants.h>

// Problem constants
#define ROWS_TOTAL 16384   // B*W = 256*64
#define WIN  128           // w_embedding dim
#define HID  256           // 2*W_IN hidden
#define IDIM 64
#define ODIM 64
#define TM   64            // rows per CTA
#define SB   68            // shB row stride (floats), padded vs 64

__global__ __launch_bounds__(256, 1)
void bnaf_fused_kernel(const float* __restrict__ g_input,
                       const float* __restrict__ g_wemb,
                       const float* __restrict__ g_logj,
                       const float* __restrict__ w_w1,
                       const float* __restrict__ w_b1,
                       const float* __restrict__ w_w2,
                       const float* __restrict__ w_b2,
                       const float* __restrict__ b_w1,
                       const float* __restrict__ b_b1,
                       const float* __restrict__ b_w2,
                       const float* __restrict__ b_b2,
                       float* __restrict__ g_out)
{
    extern __shared__ float smem[];
    float* sh_h   = smem;                    // TM*HID   = 16384 floats
    float* sh_emb = sh_h   + TM * HID;       // TM*WIN   = 8192
    float* sh_B   = sh_emb + TM * WIN;       // TM*SB    = 4352
    float* sh_in  = sh_B   + TM * SB;        // TM*IDIM  = 4096
    float* sh_lj  = sh_in  + TM * IDIM;      // TM*IDIM  = 4096
    float* sh_wb2 = sh_lj  + TM * IDIM;      // IDIM*ODIM= 4096

    const int tid = threadIdx.x;
    const int cta = blockIdx.x;
    const size_t rbase = (size_t)cta * TM;

    // ---------------- Phase 0: stage inputs ----------------
    {
        const float4* g = (const float4*)(g_wemb + rbase * WIN);
        float4* s = (float4*)sh_emb;
        #pragma unroll
        for (int st = 0; st < 8; ++st) s[tid + st * 256] = g[tid + st * 256];
    }
    {
        const float4* g = (const float4*)(g_input + rbase * IDIM);
        float4* s = (float4*)sh_in;
        #pragma unroll
        for (int st = 0; st < 4; ++st) s[tid + st * 256] = g[tid + st * 256];
    }
    {
        const float4* g = (const float4*)(g_logj + rbase * IDIM);
        float4* s = (float4*)sh_lj;
        #pragma unroll
        for (int st = 0; st < 4; ++st) s[tid + st * 256] = g[tid + st * 256];
    }
    {
        const float4* g = (const float4*)(w_b2);
        float4* s = (float4*)sh_wb2;
        #pragma unroll
        for (int st = 0; st < 4; ++st) s[tid + st * 256] = g[tid + st * 256];
    }
    __syncthreads();

    // ---------------- Phase 1 helper: h = tanh(emb @ net1^T + bias) ----------------
    // thread tid owns hidden unit j = tid; processes rows in 4 chunks of 16.
    auto compute_h = [&](const float* __restrict__ n1, const float* __restrict__ nb1) {
        const float bias = __ldg(nb1 + tid);
        #pragma unroll 1
        for (int rc = 0; rc < 4; ++rc) {
            float acc[16];
            #pragma unroll
            for (int rr = 0; rr < 16; ++rr) acc[rr] = bias;
            #pragma unroll 4
            for (int k = 0; k < WIN; k += 4) {
                const float4 wv = __ldg((const float4*)(n1 + tid * WIN + k));
                #pragma unroll
                for (int rr = 0; rr < 16; ++rr) {
                    const float4 ev = *(const float4*)&sh_emb[(rc * 16 + rr) * WIN + k];
                    acc[rr] = fmaf(ev.x, wv.x, acc[rr]);
                    acc[rr] = fmaf(ev.y, wv.y, acc[rr]);
                    acc[rr] = fmaf(ev.z, wv.z, acc[rr]);
                    acc[rr] = fmaf(ev.w, wv.w, acc[rr]);
                }
            }
            #pragma unroll
            for (int rr = 0; rr < 16; ++rr)
                sh_h[(rc * 16 + rr) * HID + tid] = tanhf(acc[rr]);
        }
    };

    // cell ownership: 4 rows x 4 outputs per thread
    const int r0 = ((tid >> 4) << 2);   // 0,4,...,60
    const int o0 = ((tid & 15) << 2);   // 0,4,...,60

    float outA[16], mA[16], sA[16];

    // ---------------- Phase 1b: h_b, then b1 -> init output accumulators ----------------
    compute_h(b_w1, b_b1);
    __syncthreads();
    {
        float acc[16];
        #pragma unroll
        for (int c = 0; c < 16; ++c) acc[c] = 0.f;
        #pragma unroll 4
        for (int k = 0; k < HID; k += 4) {
            float4 a[4], b[4];
            #pragma unroll
            for (int ri = 0; ri < 4; ++ri)
                a[ri] = *(const float4*)&sh_h[(r0 + ri) * HID + k];
            #pragma unroll
            for (int oi = 0; oi < 4; ++oi)
                b[oi] = __ldg((const float4*)(b_w2 + (o0 + oi) * HID + k));
            #pragma unroll
            for (int ri = 0; ri < 4; ++ri)
                #pragma unroll
                for (int oi = 0; oi < 4; ++oi) {
                    int c = ri * 4 + oi;
                    acc[c] = fmaf(a[ri].x, b[oi].x, acc[c]);
                    acc[c] = fmaf(a[ri].y, b[oi].y, acc[c]);
                    acc[c] = fmaf(a[ri].z, b[oi].z, acc[c]);
                    acc[c] = fmaf(a[ri].w, b[oi].w, acc[c]);
                }
        }
        #pragma unroll
        for (int ri = 0; ri < 4; ++ri)
            #pragma unroll
            for (int oi = 0; oi < 4; ++oi) {
                int c = ri * 4 + oi;
                outA[c] = acc[c] + __ldg(b_b2 + o0 + oi);
                mA[c] = -CUDART_INF_F;
                sA[c] = 0.f;
            }
    }
    __syncthreads();   // done reading h_b before overwrite

    // ---------------- Phase 1c: h_w ----------------
    compute_h(w_w1, w_b1);
    __syncthreads();

    // ---------------- Main loop over i ----------------
    #pragma unroll 1
    for (int i = 0; i < IDIM; ++i) {
        float w1a[16];
        #pragma unroll
        for (int c = 0; c < 16; ++c) w1a[c] = 0.f;

        const float4* gB = (const float4*)(w_w2 + (size_t)i * ODIM * HID);

        #pragma unroll 1
        for (int kc = 0; kc < 4; ++kc) {
            // stage w_w2 rows [i*64 .. i*64+63], k-slice [kc*64, kc*64+64)
            #pragma unroll
            for (int st = 0; st < 4; ++st) {
                int idx = tid + st * 256;      // 0..1023
                int row = idx >> 4;            // 0..63
                int c4  = idx & 15;            // 0..15
                float4 v = gB[row * (HID / 4) + kc * 16 + c4];
                *(float4*)&sh_B[row * SB + c4 * 4] = v;
            }
            __syncthreads();

            const float* hrow = sh_h + kc * 64;
            #pragma unroll
            for (int kk = 0; kk < 64; kk += 4) {
                float4 a[4], b[4];
                #pragma unroll
                for (int ri = 0; ri < 4; ++ri)
                    a[ri] = *(const float4*)&hrow[(r0 + ri) * HID + kk];
                #pragma unroll
                for (int oi = 0; oi < 4; ++oi)
                    b[oi] = *(const float4*)&sh_B[(o0 + oi) * SB + kk];
                #pragma unroll
                for (int ri = 0; ri < 4; ++ri)
                    #pragma unroll
                    for (int oi = 0; oi < 4; ++oi) {
                        int c = ri * 4 + oi;
                        w1a[c] = fmaf(a[ri].x, b[oi].x, w1a[c]);
                        w1a[c] = fmaf(a[ri].y, b[oi].y, w1a[c]);
                        w1a[c] = fmaf(a[ri].z, b[oi].z, w1a[c]);
                        w1a[c] = fmaf(a[ri].w, b[oi].w, w1a[c]);
                    }
            }
            __syncthreads();   // protect sh_B before next stage
        }

        // fused epilogue for this i: exp-weighted sum + online logsumexp
        #pragma unroll
        for (int ri = 0; ri < 4; ++ri) {
            const float inp = sh_in[(r0 + ri) * IDIM + i];
            const float lj  = sh_lj[(r0 + ri) * IDIM + i];
            #pragma unroll
            for (int oi = 0; oi < 4; ++oi) {
                const int c = ri * 4 + oi;
                const float w1 = w1a[c] + sh_wb2[i * ODIM + o0 + oi];
                outA[c] = fmaf(inp, __expf(w1), outA[c]);
                const float z  = w1 + lj;
                const float mn = fmaxf(mA[c], z);
                sA[c] = sA[c] * __expf(mA[c] - mn) + __expf(z - mn);
                mA[c] = mn;
            }
        }
    }

    // ---------------- Store: output then logj_out ----------------
    #pragma unroll
    for (int ri = 0; ri < 4; ++ri) {
        const size_t row = rbase + r0 + ri;
        float4 ov, lv;
        ov.x = outA[ri * 4 + 0]; ov.y = outA[ri * 4 + 1];
        ov.z = outA[ri * 4 + 2]; ov.w = outA[ri * 4 + 3];
        lv.x = mA[ri * 4 + 0] + logf(sA[ri * 4 + 0]);
        lv.y = mA[ri * 4 + 1] + logf(sA[ri * 4 + 1]);
        lv.z = mA[ri * 4 + 2] + logf(sA[ri * 4 + 2]);
        lv.w = mA[ri * 4 + 3] + logf(sA[ri * 4 + 3]);
        *(float4*)&g_out[row * ODIM + o0] = ov;
        *(float4*)&g_out[(size_t)ROWS_TOTAL * ODIM + row * ODIM + o0] = lv;
    }
}

extern "C" void kernel_launch(void* const* d_in, const int* in_sizes, int n_in,
                              void* d_out, int out_size)
{
    const float* input = (const float*)d_in[0];
    const float* wemb  = (const float*)d_in[1];
    const float* logj  = (const float*)d_in[2];
    const float* w_w1  = (const float*)d_in[3];
    const float* w_b1  = (const float*)d_in[4];
    const float* w_w2  = (const float*)d_in[5];
    const float* w_b2  = (const float*)d_in[6];
    const float* b_w1  = (const float*)d_in[7];
    const float* b_b1  = (const float*)d_in[8];
    const float* b_w2  = (const float*)d_in[9];
    const float* b_b2  = (const float*)d_in[10];
    float* out = (float*)d_out;

    const int smem_bytes = (TM*HID + TM*WIN + TM*SB + TM*IDIM + TM*IDIM + IDIM*ODIM) * sizeof(float);
    cudaFuncSetAttribute(bnaf_fused_kernel,
                         cudaFuncAttributeMaxDynamicSharedMemorySize, smem_bytes);

    bnaf_fused_kernel<<<ROWS_TOTAL / TM, 256, smem_bytes>>>(
        input, wemb, logj,
        w_w1, w_b1, w_w2, w_b2,
        b_w1, b_b1, b_w2, b_b2,
        out);
}

// round 2
// speedup vs baseline: 1.0002x; 1.0002x over previous
#include <cuda_runtime.h>
#include <math_constants.h>

// Problem constants
#define ROWS_TOTAL 16384   // B*W = 256*64
#define WIN  128           // w_embedding dim
#define HID  256           // 2*W_IN hidden
#define IDIM 64
#define ODIM 64
#define TM   64            // rows per CTA
#define SB   68            // shB row stride (floats), padded vs 64

__global__ __launch_bounds__(256, 1)
void bnaf_fused_kernel(const float* __restrict__ g_input,
                       const float* __restrict__ g_wemb,
                       const float* __restrict__ g_logj,
                       const float* __restrict__ w_w1,
                       const float* __restrict__ w_b1,
                       const float* __restrict__ w_w2,
                       const float* __restrict__ w_b2,
                       const float* __restrict__ b_w1,
                       const float* __restrict__ b_b1,
                       const float* __restrict__ b_w2,
                       const float* __restrict__ b_b2,
                       float* __restrict__ g_out)
{
    extern __shared__ float smem[];
    float* sh_h   = smem;                    // TM*HID   = 16384 floats
    float* sh_emb = sh_h   + TM * HID;       // TM*WIN   = 8192
    float* sh_B   = sh_emb + TM * WIN;       // TM*SB    = 4352
    float* sh_in  = sh_B   + TM * SB;        // TM*IDIM  = 4096
    float* sh_lj  = sh_in  + TM * IDIM;      // TM*IDIM  = 4096
    float* sh_wb2 = sh_lj  + TM * IDIM;      // IDIM*ODIM= 4096

    const int tid = threadIdx.x;
    const int cta = blockIdx.x;
    const size_t rbase = (size_t)cta * TM;

    // ---------------- Phase 0: stage inputs ----------------
    {
        const float4* g = (const float4*)(g_wemb + rbase * WIN);
        float4* s = (float4*)sh_emb;
        #pragma unroll
        for (int st = 0; st < 8; ++st) s[tid + st * 256] = g[tid + st * 256];
    }
    {
        const float4* g = (const float4*)(g_input + rbase * IDIM);
        float4* s = (float4*)sh_in;
        #pragma unroll
        for (int st = 0; st < 4; ++st) s[tid + st * 256] = g[tid + st * 256];
    }
    {
        const float4* g = (const float4*)(g_logj + rbase * IDIM);
        float4* s = (float4*)sh_lj;
        #pragma unroll
        for (int st = 0; st < 4; ++st) s[tid + st * 256] = g[tid + st * 256];
    }
    {
        const float4* g = (const float4*)(w_b2);
        float4* s = (float4*)sh_wb2;
        #pragma unroll
        for (int st = 0; st < 4; ++st) s[tid + st * 256] = g[tid + st * 256];
    }
    __syncthreads();

    // ---------------- Phase 1 helper: h = tanh(emb @ net1^T + bias) ----------------
    // thread tid owns hidden unit j = tid; processes rows in 4 chunks of 16.
    auto compute_h = [&](const float* __restrict__ n1, const float* __restrict__ nb1) {
        const float bias = __ldg(nb1 + tid);
        #pragma unroll 1
        for (int rc = 0; rc < 4; ++rc) {
            float acc[16];
            #pragma unroll
            for (int rr = 0; rr < 16; ++rr) acc[rr] = bias;
            #pragma unroll 4
            for (int k = 0; k < WIN; k += 4) {
                const float4 wv = __ldg((const float4*)(n1 + tid * WIN + k));
                #pragma unroll
                for (int rr = 0; rr < 16; ++rr) {
                    const float4 ev = *(const float4*)&sh_emb[(rc * 16 + rr) * WIN + k];
                    acc[rr] = fmaf(ev.x, wv.x, acc[rr]);
                    acc[rr] = fmaf(ev.y, wv.y, acc[rr]);
                    acc[rr] = fmaf(ev.z, wv.z, acc[rr]);
                    acc[rr] = fmaf(ev.w, wv.w, acc[rr]);
                }
            }
            #pragma unroll
            for (int rr = 0; rr < 16; ++rr)
                sh_h[(rc * 16 + rr) * HID + tid] = tanhf(acc[rr]);
        }
    };

    // cell ownership: 4 rows x 4 outputs per thread
    const int r0 = ((tid >> 4) << 2);   // 0,4,...,60
    const int o0 = ((tid & 15) << 2);   // 0,4,...,60

    float outA[16], mA[16], sA[16];

    // ---------------- Phase 1b: h_b, then b1 -> init output accumulators ----------------
    compute_h(b_w1, b_b1);
    __syncthreads();
    {
        float acc[16];
        #pragma unroll
        for (int c = 0; c < 16; ++c) acc[c] = 0.f;
        #pragma unroll 4
        for (int k = 0; k < HID; k += 4) {
            float4 a[4], b[4];
            #pragma unroll
            for (int ri = 0; ri < 4; ++ri)
                a[ri] = *(const float4*)&sh_h[(r0 + ri) * HID + k];
            #pragma unroll
            for (int oi = 0; oi < 4; ++oi)
                b[oi] = __ldg((const float4*)(b_w2 + (o0 + oi) * HID + k));
            #pragma unroll
            for (int ri = 0; ri < 4; ++ri)
                #pragma unroll
                for (int oi = 0; oi < 4; ++oi) {
                    int c = ri * 4 + oi;
                    acc[c] = fmaf(a[ri].x, b[oi].x, acc[c]);
                    acc[c] = fmaf(a[ri].y, b[oi].y, acc[c]);
                    acc[c] = fmaf(a[ri].z, b[oi].z, acc[c]);
                    acc[c] = fmaf(a[ri].w, b[oi].w, acc[c]);
                }
        }
        #pragma unroll
        for (int ri = 0; ri < 4; ++ri)
            #pragma unroll
            for (int oi = 0; oi < 4; ++oi) {
                int c = ri * 4 + oi;
                outA[c] = acc[c] + __ldg(b_b2 + o0 + oi);
                mA[c] = -CUDART_INF_F;
                sA[c] = 0.f;
            }
    }
    __syncthreads();   // done reading h_b before overwrite

    // ---------------- Phase 1c: h_w ----------------
    compute_h(w_w1, w_b1);
    __syncthreads();

    // ---------------- Main loop over i ----------------
    #pragma unroll 1
    for (int i = 0; i < IDIM; ++i) {
        float w1a[16];
        #pragma unroll
        for (int c = 0; c < 16; ++c) w1a[c] = 0.f;

        const float4* gB = (const float4*)(w_w2 + (size_t)i * ODIM * HID);

        #pragma unroll 1
        for (int kc = 0; kc < 4; ++kc) {
            // stage w_w2 rows [i*64 .. i*64+63], k-slice [kc*64, kc*64+64)
            #pragma unroll
            for (int st = 0; st < 4; ++st) {
                int idx = tid + st * 256;      // 0..1023
                int row = idx >> 4;            // 0..63
                int c4  = idx & 15;            // 0..15
                float4 v = gB[row * (HID / 4) + kc * 16 + c4];
                *(float4*)&sh_B[row * SB + c4 * 4] = v;
            }
            __syncthreads();

            const float* hrow = sh_h + kc * 64;
            #pragma unroll
            for (int kk = 0; kk < 64; kk += 4) {
                float4 a[4], b[4];
                #pragma unroll
                for (int ri = 0; ri < 4; ++ri)
                    a[ri] = *(const float4*)&hrow[(r0 + ri) * HID + kk];
                #pragma unroll
                for (int oi = 0; oi < 4; ++oi)
                    b[oi] = *(const float4*)&sh_B[(o0 + oi) * SB + kk];
                #pragma unroll
                for (int ri = 0; ri < 4; ++ri)
                    #pragma unroll
                    for (int oi = 0; oi < 4; ++oi) {
                        int c = ri * 4 + oi;
                        w1a[c] = fmaf(a[ri].x, b[oi].x, w1a[c]);
                        w1a[c] = fmaf(a[ri].y, b[oi].y, w1a[c]);
                        w1a[c] = fmaf(a[ri].z, b[oi].z, w1a[c]);
                        w1a[c] = fmaf(a[ri].w, b[oi].w, w1a[c]);
                    }
            }
            __syncthreads();   // protect sh_B before next stage
        }

        // fused epilogue for this i: exp-weighted sum + online logsumexp
        #pragma unroll
        for (int ri = 0; ri < 4; ++ri) {
            const float inp = sh_in[(r0 + ri) * IDIM + i];
            const float lj  = sh_lj[(r0 + ri) * IDIM + i];
            #pragma unroll
            for (int oi = 0; oi < 4; ++oi) {
                const int c = ri * 4 + oi;
                const float w1 = w1a[c] + sh_wb2[i * ODIM + o0 + oi];
                outA[c] = fmaf(inp, __expf(w1), outA[c]);
                const float z  = w1 + lj;
                const float mn = fmaxf(mA[c], z);
                sA[c] = sA[c] * __expf(mA[c] - mn) + __expf(z - mn);
                mA[c] = mn;
            }
        }
    }

    // ---------------- Store: output then logj_out ----------------
    #pragma unroll
    for (int ri = 0; ri < 4; ++ri) {
        const size_t row = rbase + r0 + ri;
        float4 ov, lv;
        ov.x = outA[ri * 4 + 0]; ov.y = outA[ri * 4 + 1];
        ov.z = outA[ri * 4 + 2]; ov.w = outA[ri * 4 + 3];
        lv.x = mA[ri * 4 + 0] + logf(sA[ri * 4 + 0]);
        lv.y = mA[ri * 4 + 1] + logf(sA[ri * 4 + 1]);
        lv.z = mA[ri * 4 + 2] + logf(sA[ri * 4 + 2]);
        lv.w = mA[ri * 4 + 3] + logf(sA[ri * 4 + 3]);
        *(float4*)&g_out[row * ODIM + o0] = ov;
        *(float4*)&g_out[(size_t)ROWS_TOTAL * ODIM + row * ODIM + o0] = lv;
    }
}

extern "C" void kernel_launch(void* const* d_in, const int* in_sizes, int n_in,
                              void* d_out, int out_size)
{
    const float* input = (const float*)d_in[0];
    const float* wemb  = (const float*)d_in[1];
    const float* logj  = (const float*)d_in[2];
    const float* w_w1  = (const float*)d_in[3];
    const float* w_b1  = (const float*)d_in[4];
    const float* w_w2  = (const float*)d_in[5];
    const float* w_b2  = (const float*)d_in[6];
    const float* b_w1  = (const float*)d_in[7];
    const float* b_b1  = (const float*)d_in[8];
    const float* b_w2  = (const float*)d_in[9];
    const float* b_b2  = (const float*)d_in[10];
    float* out = (float*)d_out;

    const int smem_bytes = (TM*HID + TM*WIN + TM*SB + TM*IDIM + TM*IDIM + IDIM*ODIM) * sizeof(float);
    cudaFuncSetAttribute(bnaf_fused_kernel,
                         cudaFuncAttributeMaxDynamicSharedMemorySize, smem_bytes);

    bnaf_fused_kernel<<<ROWS_TOTAL / TM, 256, smem_bytes>>>(
        input, wemb, logj,
        w_w1, w_b1, w_w2, w_b2,
        b_w1, b_b1, b_w2, b_b2,
        out);
}

// round 4
// speedup vs baseline: 19.6130x; 19.6098x over previous
#include <cuda_runtime.h>
#include <cstdint>

#define ROWS 16384
#define NCHUNK 64

#if defined(__CUDA_ARCH__) && (defined(__CUDA_ARCH_FEAT_SM103_ALL) || defined(__CUDA_ARCH_FEAT_SM100_ALL) || defined(__CUDA_ARCH_FEAT_SM101_ALL))
#define HAS_TC 1
#else
#define HAS_TC 0
#endif

// ---- static scratch (no allocations) ----
__device__ __align__(1024) unsigned char g_w2img[NCHUNK * 32768]; // w_w2 chunks: 64 x (64r x 256c bf16)
__device__ __align__(1024) unsigned char g_w1img[65536];          // w_w1: 256x128 bf16 image
__device__ __align__(1024) unsigned char g_bw1img[65536];         // b_w1: 256x128
__device__ __align__(1024) unsigned char g_bw2img[32768];         // b_w2: 64x256

// ---- helpers usable on all targets ----
__device__ __forceinline__ uint32_t swz(uint32_t b) { return b ^ ((b >> 3) & 0x70); }
__device__ __forceinline__ uint32_t imgoff(int row, int col, int natoms) {
    return (uint32_t)(((row >> 3) + (col >> 6) * natoms) * 1024 + (row & 7) * 128 + (col & 63) * 2);
}
__device__ __forceinline__ uint32_t packbf(float lo, float hi) {
    uint32_t r; asm("cvt.rn.bf16x2.f32 %0, %1, %2;" : "=r"(r) : "f"(hi), "f"(lo)); return r;
}
__device__ __forceinline__ float tanh_ap(float x) { float y; asm("tanh.approx.f32 %0, %1;" : "=f"(y) : "f"(x)); return y; }

// ================= P0: build bf16 weight images =================
__global__ void p0(const float* __restrict__ w_w1, const float* __restrict__ w_w2,
                   const float* __restrict__ b_w1, const float* __restrict__ b_w2)
{
    const int t = blockIdx.x * blockDim.x + threadIdx.x;
    const int NT = gridDim.x * blockDim.x;
    for (int p = t; p < NCHUNK * 64 * 128; p += NT) {           // w_w2 chunks (natoms=8)
        int ch = p >> 13, rem = p & 8191, row = rem >> 7, col = (rem & 127) * 2;
        int n = ch * 64 + row;
        *(uint32_t*)&g_w2img[ch * 32768u + swz(imgoff(row, col, 8))] =
            packbf(w_w2[n * 256 + col], w_w2[n * 256 + col + 1]);
    }
    for (int p = t; p < 256 * 64; p += NT) {                    // w_w1 / b_w1 (natoms=32)
        int row = p >> 6, col = (p & 63) * 2;
        uint32_t off = swz(imgoff(row, col, 32));
        *(uint32_t*)&g_w1img[off]  = packbf(w_w1[row * 128 + col], w_w1[row * 128 + col + 1]);
        *(uint32_t*)&g_bw1img[off] = packbf(b_w1[row * 128 + col], b_w1[row * 128 + col + 1]);
    }
    for (int p = t; p < 64 * 128; p += NT) {                    // b_w2 (natoms=8)
        int row = p >> 7, col = (p & 127) * 2;
        *(uint32_t*)&g_bw2img[swz(imgoff(row, col, 8))] =
            packbf(b_w2[row * 256 + col], b_w2[row * 256 + col + 1]);
    }
}

#if HAS_TC
// ---- tcgen05-only helpers ----
__device__ __forceinline__ uint32_t s2u(const void* p) {
    uint32_t a; asm("{ .reg .u64 t; cvta.to.shared.u64 t, %1; cvt.u32.u64 %0, t; }" : "=r"(a) : "l"(p)); return a;
}
__device__ __forceinline__ uint32_t elect1() {
    uint32_t p; asm volatile("{\n\t.reg .pred p;\n\telect.sync _|p, 0xFFFFFFFF;\n\tselp.b32 %0,1,0,p;\n\t}" : "=r"(p)); return p;
}
__device__ __forceinline__ uint64_t mkdesc(uint32_t a) {
    return ((uint64_t)2 << 61) | ((uint64_t)1 << 46) | ((uint64_t)64 << 32) | ((uint64_t)1 << 16) | ((uint64_t)(a >> 4) & 0x3FFF);
}
__device__ __forceinline__ void mma_ss(uint32_t d, uint64_t ad, uint64_t bd, uint32_t idesc, uint32_t en) {
    asm volatile("{\n\t.reg .pred p;\n\tsetp.ne.u32 p, %5, 0;\n\t"
        "tcgen05.mma.cta_group::1.kind::f16 [%0], %1, %2, %3, {%4,%4,%4,%4}, p;\n\t}"
        :: "r"(d), "l"(ad), "l"(bd), "r"(idesc), "r"(0u), "r"(en) : "memory");
}
__device__ __forceinline__ void issue_gemm(uint32_t d, uint64_t ad, uint64_t bd, int nks,
                                           uint32_t astr, uint32_t bstr, uint32_t idesc) {
    for (int ks = 0; ks < nks; ++ks)
        mma_ss(d, ad + (ks & 3) * 2 + (ks >> 2) * astr, bd + (ks & 3) * 2 + (ks >> 2) * bstr, idesc, ks > 0);
}
#define TC_COMMIT(mb) asm volatile("tcgen05.commit.cta_group::1.mbarrier::arrive::one.shared::cluster.b64 [%0];" :: "r"(mb) : "memory")
#define TC_WAIT_LD()  asm volatile("tcgen05.wait::ld.sync.aligned;" ::: "memory")
#define TC_FA()       asm volatile("tcgen05.fence::after_thread_sync;" ::: "memory")
#define TC_FB()       asm volatile("tcgen05.fence::before_thread_sync;" ::: "memory")
#define FPROXY()      asm volatile("fence.proxy.async.shared::cta;" ::: "memory")
#define MBAR_INIT(mb) asm volatile("mbarrier.init.shared.b64 [%0], 1;" :: "r"(mb) : "memory")
#define MBAR_WAIT(mb, par) do {                                                        \
    uint32_t _m = (mb), _p = (par), _d;                                                \
    asm volatile("{\n\t.reg .pred p;\n\t"                                              \
      "mbarrier.try_wait.parity.acquire.cta.shared::cta.b64 p, [%1], %2;\n\t"          \
      "selp.b32 %0,1,0,p;\n\t}" : "=r"(_d) : "r"(_m), "r"(_p) : "memory");             \
    if (!_d) { asm volatile("{\n\t.reg .pred P1;\n\tWL_%=:\n\t"                        \
      "mbarrier.try_wait.parity.acquire.cta.shared::cta.b64 P1, [%0], %1, 0x989680;\n\t" \
      "@P1 bra.uni WD_%=;\n\tbra.uni WL_%=;\n\tWD_%=:\n\t}" :: "r"(_m), "r"(_p) : "memory"); } \
} while (0)
#define LDTM32(r, a)                                                                   \
    asm volatile("tcgen05.ld.sync.aligned.32x32b.x32.b32 "                             \
      "{%0,%1,%2,%3,%4,%5,%6,%7,%8,%9,%10,%11,%12,%13,%14,%15,"                        \
      "%16,%17,%18,%19,%20,%21,%22,%23,%24,%25,%26,%27,%28,%29,%30,%31}, [%32];"       \
      : "=r"((r)[0]),"=r"((r)[1]),"=r"((r)[2]),"=r"((r)[3]),"=r"((r)[4]),"=r"((r)[5]), \
        "=r"((r)[6]),"=r"((r)[7]),"=r"((r)[8]),"=r"((r)[9]),"=r"((r)[10]),"=r"((r)[11]),\
        "=r"((r)[12]),"=r"((r)[13]),"=r"((r)[14]),"=r"((r)[15]),"=r"((r)[16]),"=r"((r)[17]),\
        "=r"((r)[18]),"=r"((r)[19]),"=r"((r)[20]),"=r"((r)[21]),"=r"((r)[22]),"=r"((r)[23]),\
        "=r"((r)[24]),"=r"((r)[25]),"=r"((r)[26]),"=r"((r)[27]),"=r"((r)[28]),"=r"((r)[29]),\
        "=r"((r)[30]),"=r"((r)[31]) : "r"(a))

#define IDESC_N64  0x8100490u
#define IDESC_N256 0x8400490u
#endif // HAS_TC

// smem map (bytes) for the tcgen05 path
#define SM_A    1024u      // emb A-image 32K -> later b_w2 image 32K
#define SM_HW   33792u     // w_w1/b_w1 B-image 64K -> later h_w image
#define SM_HB   99328u     // h_b image 64K -> later B chunk double buffer (2x32K)
#define SM_INT  164864u    // input-T 64x129 f32
#define SM_LJT  197888u    // logj-T 64x129 f32
#define SM_TOT  230912u

// ================= main fused kernel =================
__global__ __launch_bounds__(256, 1)
void bnaf_tc(const float* __restrict__ g_input, const float* __restrict__ g_wemb,
             const float* __restrict__ g_logj,
             const float* __restrict__ w_w1, const float* __restrict__ w_b1,
             const float* __restrict__ w_w2, const float* __restrict__ w_b2,
             const float* __restrict__ b_w1, const float* __restrict__ b_b1,
             const float* __restrict__ b_w2, const float* __restrict__ b_b2,
             float* __restrict__ g_out)
{
#if HAS_TC
    extern __shared__ __align__(1024) unsigned char sm[];
    const uint32_t sb = s2u(sm);
    const int tid = threadIdx.x, wid = tid >> 5, lane = tid & 31;
    const int rowid = (wid & 3) * 32 + lane;          // owned D row
    const int cbase = (wid >> 2) * 32;                // owned col half
    const size_t rbase = (size_t)blockIdx.x * 128;
    const uint32_t mbh = sb + 16, mb0 = sb + 24, mb1 = sb + 32;

    if (wid == 0) asm volatile("tcgen05.alloc.cta_group::1.sync.aligned.shared::cta.b32 [%0], 512;" :: "r"(sb) : "memory");
    if (tid == 0) { MBAR_INIT(mbh); MBAR_INIT(mb0); MBAR_INIT(mb1); }

    // stage emb A-image (M=128,K=128,natoms=16)
    for (int p = tid; p < 128 * 64; p += 256) {
        int row = p >> 6, col = (p & 63) * 2;
        float2 v = *(const float2*)&g_wemb[(rbase + row) * 128 + col];
        *(uint32_t*)&sm[SM_A + swz(imgoff(row, col, 16))] = packbf(v.x, v.y);
    }
    // copy w_w1 image
    { const uint4* s = (const uint4*)g_w1img; uint4* d = (uint4*)(sm + SM_HW);
      for (int j = tid; j < 4096; j += 256) d[j] = s[j]; }
    // stage input-T / logj-T (pad 129)
    {
        float* sin = (float*)(sm + SM_INT); float* slj = (float*)(sm + SM_LJT);
        for (int p = tid; p < 8192; p += 256) {
            int row = p >> 6, col = p & 63;
            sin[col * 129 + row] = g_input[(rbase + row) * 64 + col];
            slj[col * 129 + row] = g_logj [(rbase + row) * 64 + col];
        }
    }
    FPROXY(); __syncthreads();
    const uint32_t tb = *(const uint32_t*)&sm[0];

    // ---- MMA: h_w pre-act -> D[256..511]
    if (wid == 0 && elect1()) { issue_gemm(tb + 256, mkdesc(sb + SM_A), mkdesc(sb + SM_HW), 8, 1024, 2048, IDESC_N256); TC_COMMIT(mbh); }
    MBAR_WAIT(mbh, 0);
    // swap B -> b_w1
    { const uint4* s = (const uint4*)g_bw1img; uint4* d = (uint4*)(sm + SM_HW);
      for (int j = tid; j < 4096; j += 256) d[j] = s[j]; }
    FPROXY(); __syncthreads();
    // ---- MMA: h_b pre-act -> D[0..255]
    if (wid == 0 && elect1()) { issue_gemm(tb + 0, mkdesc(sb + SM_A), mkdesc(sb + SM_HW), 8, 1024, 2048, IDESC_N256); TC_COMMIT(mbh); }
    MBAR_WAIT(mbh, 1); TC_FA();

    // h_b: tanh(pre + b_b1) -> bf16 image at SM_HB (natoms=16)
    {
        const int chalf = (wid >> 2) * 128;
        for (int j = 0; j < 4; ++j) {
            uint32_t r[32]; LDTM32(r, tb + 0 + chalf + j * 32); TC_WAIT_LD();
            const int cb = chalf + j * 32;
            #pragma unroll
            for (int c = 0; c < 32; c += 2) {
                float p0v = __uint_as_float(r[c])     + __ldg(b_b1 + cb + c);
                float p1v = __uint_as_float(r[c + 1]) + __ldg(b_b1 + cb + c + 1);
                *(uint32_t*)&sm[SM_HB + swz(imgoff(rowid, cb + c, 16))] = packbf(tanh_ap(p0v), tanh_ap(p1v));
            }
        }
    }
    // b_w2 image -> SM_A (emb dead)
    { const uint4* s = (const uint4*)g_bw2img; uint4* d = (uint4*)(sm + SM_A);
      for (int j = tid; j < 2048; j += 256) d[j] = s[j]; }
    TC_FB(); FPROXY(); __syncthreads();
    // ---- MMA: b1 -> D[0..63]
    if (wid == 0 && elect1()) { TC_FA(); issue_gemm(tb + 0, mkdesc(sb + SM_HB), mkdesc(sb + SM_A), 16, 1024, 512, IDESC_N64); TC_COMMIT(mbh); }
    MBAR_WAIT(mbh, 0); TC_FA();

    float outA[32], lsum[32];
    {   // read b1, init accumulators
        uint32_t r[32]; LDTM32(r, tb + 0 + cbase); TC_WAIT_LD();
        #pragma unroll
        for (int c = 0; c < 32; ++c) { outA[c] = __uint_as_float(r[c]) + __ldg(b_b2 + cbase + c); lsum[c] = 0.f; }
    }
    // h_w: tanh(pre + w_b1) -> bf16 image at SM_HW (b_w1 dead)
    {
        const int chalf = (wid >> 2) * 128;
        for (int j = 0; j < 4; ++j) {
            uint32_t r[32]; LDTM32(r, tb + 256 + chalf + j * 32); TC_WAIT_LD();
            const int cb = chalf + j * 32;
            #pragma unroll
            for (int c = 0; c < 32; c += 2) {
                float p0v = __uint_as_float(r[c])     + __ldg(w_b1 + cb + c);
                float p1v = __uint_as_float(r[c + 1]) + __ldg(w_b1 + cb + c + 1);
                *(uint32_t*)&sm[SM_HW + swz(imgoff(rowid, cb + c, 16))] = packbf(tanh_ap(p0v), tanh_ap(p1v));
            }
        }
    }
    __syncthreads();
    // stage B chunks 0,1 (h_b image dead)
    {
        uint4* d = (uint4*)(sm + SM_HB);
        const uint4* s0 = (const uint4*)(g_w2img);
        const uint4* s1 = (const uint4*)(g_w2img + 32768);
        for (int j = tid; j < 2048; j += 256) { d[j] = s0[j]; d[j + 2048] = s1[j]; }
    }
    TC_FB(); FPROXY(); __syncthreads();
    const uint64_t hwdesc = mkdesc(sb + SM_HW);
    if (wid == 0 && elect1()) { TC_FA(); issue_gemm(tb + 0, hwdesc, mkdesc(sb + SM_HB), 16, 1024, 512, IDESC_N64); TC_COMMIT(mb0); }

    const float* sin = (const float*)(sm + SM_INT);
    const float* slj = (const float*)(sm + SM_LJT);

    #pragma unroll 1
    for (int i = 0; i < NCHUNK; ++i) {
        // overlap: issue MMA(i+1) before waiting on MMA(i)
        if (i + 1 < NCHUNK && wid == 0 && elect1()) {
            issue_gemm(tb + ((i + 1) & 1) * 64, hwdesc, mkdesc(sb + SM_HB + ((i + 1) & 1) * 32768), 16, 1024, 512, IDESC_N64);
            TC_COMMIT((i + 1) & 1 ? mb1 : mb0);
        }
        MBAR_WAIT((i & 1) ? mb1 : mb0, (i >> 1) & 1);
        TC_FA();
        uint32_t r[32];
        LDTM32(r, tb + (i & 1) * 64 + cbase);
        // stage B(i+2) over B(i)'s buffer while the LDTM drains
        if (i + 2 < NCHUNK) {
            uint4* d = (uint4*)(sm + SM_HB + (i & 1) * 32768);
            const uint4* s = (const uint4*)(g_w2img + (size_t)(i + 2) * 32768);
            for (int j = tid; j < 2048; j += 256) d[j] = s[j];
        }
        TC_WAIT_LD();
        const float inp = sin[i * 129 + rowid];
        const float el  = __expf(slj[i * 129 + rowid]);
        #pragma unroll
        for (int c = 0; c < 32; ++c) {
            float w1 = __uint_as_float(r[c]) + __ldg(w_b2 + i * 64 + cbase + c);
            float e = __expf(w1);
            outA[c] = fmaf(inp, e, outA[c]);
            lsum[c] = fmaf(el, e, lsum[c]);
        }
        TC_FB(); FPROXY(); __syncthreads();
    }

    // store
    {
        const size_t go = (rbase + rowid) * 64 + cbase;
        #pragma unroll
        for (int c = 0; c < 32; c += 4) {
            float4 v; v.x = outA[c]; v.y = outA[c + 1]; v.z = outA[c + 2]; v.w = outA[c + 3];
            *(float4*)&g_out[go + c] = v;
            float4 w; w.x = __logf(lsum[c]); w.y = __logf(lsum[c + 1]);
            w.z = __logf(lsum[c + 2]); w.w = __logf(lsum[c + 3]);
            *(float4*)&g_out[(size_t)ROWS * 64 + go + c] = w;
        }
    }
    __syncthreads();
    if (wid == 0) {
        asm volatile("tcgen05.relinquish_alloc_permit.cta_group::1.sync.aligned;");
        asm volatile("tcgen05.dealloc.cta_group::1.sync.aligned.b32 %0, 512;" :: "r"(tb));
    }

#else  // ===================== SIMT fallback (non-'a' targets) =====================
    extern __shared__ __align__(1024) unsigned char smraw[];
    float* fsm = (float*)smraw;
    float* sh_h   = fsm;                    // 64*256
    float* sh_emb = sh_h   + 64 * 256;      // 64*128
    float* sh_B   = sh_emb + 64 * 128;      // 64*68
    float* sh_in  = sh_B   + 64 * 68;       // 64*64
    float* sh_lj  = sh_in  + 64 * 64;       // 64*64
    float* sh_wb2 = sh_lj  + 64 * 64;       // 4096
    const int tid = threadIdx.x;
    const int r0 = ((tid >> 4) << 2);
    const int o0 = ((tid & 15) << 2);

    for (int half = 0; half < 2; ++half) {
        const size_t rbase = (size_t)blockIdx.x * 128 + half * 64;
        for (int p = tid; p < 64 * 128; p += 256) sh_emb[p] = g_wemb[rbase * 128 + p];
        for (int p = tid; p < 64 * 64;  p += 256) { sh_in[p] = g_input[rbase * 64 + p]; sh_lj[p] = g_logj[rbase * 64 + p]; }
        for (int p = tid; p < 4096;     p += 256) sh_wb2[p] = w_b2[p];
        __syncthreads();

        float outA[16], mA[16], sA[16];
        // h_b
        {
            const float bias = b_b1[tid];
            for (int rc = 0; rc < 4; ++rc) {
                float acc[16];
                #pragma unroll
                for (int rr = 0; rr < 16; ++rr) acc[rr] = bias;
                for (int k = 0; k < 128; k += 4) {
                    const float4 wv = *(const float4*)(b_w1 + tid * 128 + k);
                    #pragma unroll
                    for (int rr = 0; rr < 16; ++rr) {
                        const float4 ev = *(const float4*)&sh_emb[(rc * 16 + rr) * 128 + k];
                        acc[rr] = fmaf(ev.x, wv.x, fmaf(ev.y, wv.y, fmaf(ev.z, wv.z, fmaf(ev.w, wv.w, acc[rr]))));
                    }
                }
                #pragma unroll
                for (int rr = 0; rr < 16; ++rr) sh_h[(rc * 16 + rr) * 256 + tid] = tanhf(acc[rr]);
            }
        }
        __syncthreads();
        {
            float acc[16];
            #pragma unroll
            for (int c = 0; c < 16; ++c) acc[c] = 0.f;
            for (int k = 0; k < 256; k += 4) {
                float4 a[4], b[4];
                #pragma unroll
                for (int ri = 0; ri < 4; ++ri) a[ri] = *(const float4*)&sh_h[(r0 + ri) * 256 + k];
                #pragma unroll
                for (int oi = 0; oi < 4; ++oi) b[oi] = *(const float4*)(b_w2 + (o0 + oi) * 256 + k);
                #pragma unroll
                for (int ri = 0; ri < 4; ++ri)
                    #pragma unroll
                    for (int oi = 0; oi < 4; ++oi) {
                        int c = ri * 4 + oi;
                        acc[c] = fmaf(a[ri].x, b[oi].x, fmaf(a[ri].y, b[oi].y, fmaf(a[ri].z, b[oi].z, fmaf(a[ri].w, b[oi].w, acc[c]))));
                    }
            }
            #pragma unroll
            for (int ri = 0; ri < 4; ++ri)
                #pragma unroll
                for (int oi = 0; oi < 4; ++oi) {
                    int c = ri * 4 + oi;
                    outA[c] = acc[c] + b_b2[o0 + oi];
                    mA[c] = -__int_as_float(0x7f800000); sA[c] = 0.f;
                }
        }
        __syncthreads();
        // h_w
        {
            const float bias = w_b1[tid];
            for (int rc = 0; rc < 4; ++rc) {
                float acc[16];
                #pragma unroll
                for (int rr = 0; rr < 16; ++rr) acc[rr] = bias;
                for (int k = 0; k < 128; k += 4) {
                    const float4 wv = *(const float4*)(w_w1 + tid * 128 + k);
                    #pragma unroll
                    for (int rr = 0; rr < 16; ++rr) {
                        const float4 ev = *(const float4*)&sh_emb[(rc * 16 + rr) * 128 + k];
                        acc[rr] = fmaf(ev.x, wv.x, fmaf(ev.y, wv.y, fmaf(ev.z, wv.z, fmaf(ev.w, wv.w, acc[rr]))));
                    }
                }
                #pragma unroll
                for (int rr = 0; rr < 16; ++rr) sh_h[(rc * 16 + rr) * 256 + tid] = tanhf(acc[rr]);
            }
        }
        __syncthreads();

        for (int i = 0; i < 64; ++i) {
            float w1a[16];
            #pragma unroll
            for (int c = 0; c < 16; ++c) w1a[c] = 0.f;
            const float4* gB = (const float4*)(w_w2 + (size_t)i * 64 * 256);
            for (int kc = 0; kc < 4; ++kc) {
                #pragma unroll
                for (int st = 0; st < 4; ++st) {
                    int idx = tid + st * 256;
                    int row = idx >> 4, c4 = idx & 15;
                    *(float4*)&sh_B[row * 68 + c4 * 4] = gB[row * 64 + kc * 16 + c4];
                }
                __syncthreads();
                const float* hrow = sh_h + kc * 64;
                for (int kk = 0; kk < 64; kk += 4) {
                    float4 a[4], b[4];
                    #pragma unroll
                    for (int ri = 0; ri < 4; ++ri) a[ri] = *(const float4*)&hrow[(r0 + ri) * 256 + kk];
                    #pragma unroll
                    for (int oi = 0; oi < 4; ++oi) b[oi] = *(const float4*)&sh_B[(o0 + oi) * 68 + kk];
                    #pragma unroll
                    for (int ri = 0; ri < 4; ++ri)
                        #pragma unroll
                        for (int oi = 0; oi < 4; ++oi) {
                            int c = ri * 4 + oi;
                            w1a[c] = fmaf(a[ri].x, b[oi].x, fmaf(a[ri].y, b[oi].y, fmaf(a[ri].z, b[oi].z, fmaf(a[ri].w, b[oi].w, w1a[c]))));
                        }
                }
                __syncthreads();
            }
            #pragma unroll
            for (int ri = 0; ri < 4; ++ri) {
                const float inp = sh_in[(r0 + ri) * 64 + i];
                const float lj  = sh_lj[(r0 + ri) * 64 + i];
                #pragma unroll
                for (int oi = 0; oi < 4; ++oi) {
                    const int c = ri * 4 + oi;
                    const float w1 = w1a[c] + sh_wb2[i * 64 + o0 + oi];
                    outA[c] = fmaf(inp, __expf(w1), outA[c]);
                    const float z = w1 + lj;
                    const float mn = fmaxf(mA[c], z);
                    sA[c] = sA[c] * __expf(mA[c] - mn) + __expf(z - mn);
                    mA[c] = mn;
                }
            }
        }
        #pragma unroll
        for (int ri = 0; ri < 4; ++ri) {
            const size_t row = rbase + r0 + ri;
            float4 ov, lv;
            ov.x = outA[ri*4+0]; ov.y = outA[ri*4+1]; ov.z = outA[ri*4+2]; ov.w = outA[ri*4+3];
            lv.x = mA[ri*4+0] + logf(sA[ri*4+0]); lv.y = mA[ri*4+1] + logf(sA[ri*4+1]);
            lv.z = mA[ri*4+2] + logf(sA[ri*4+2]); lv.w = mA[ri*4+3] + logf(sA[ri*4+3]);
            *(float4*)&g_out[row * 64 + o0] = ov;
            *(float4*)&g_out[(size_t)ROWS * 64 + row * 64 + o0] = lv;
        }
        __syncthreads();
    }
#endif
}

extern "C" void kernel_launch(void* const* d_in, const int* in_sizes, int n_in,
                              void* d_out, int out_size)
{
    const float* input = (const float*)d_in[0];
    const float* wemb  = (const float*)d_in[1];
    const float* logj  = (const float*)d_in[2];
    const float* w_w1  = (const float*)d_in[3];
    const float* w_b1  = (const float*)d_in[4];
    const float* w_w2  = (const float*)d_in[5];
    const float* w_b2  = (const float*)d_in[6];
    const float* b_w1  = (const float*)d_in[7];
    const float* b_b1  = (const float*)d_in[8];
    const float* b_w2  = (const float*)d_in[9];
    const float* b_b2  = (const float*)d_in[10];

    p0<<<256, 256>>>(w_w1, w_w2, b_w1, b_w2);
    cudaFuncSetAttribute(bnaf_tc, cudaFuncAttributeMaxDynamicSharedMemorySize, SM_TOT);
    bnaf_tc<<<128, 256, SM_TOT>>>(input, wemb, logj,
                                  w_w1, w_b1, w_w2, w_b2,
                                  b_w1, b_b1, b_w2, b_b2, (float*)d_out);
}

// round 5
// speedup vs baseline: 25.5127x; 1.3008x over previous
#include <cuda_runtime.h>
#include <cstdint>

#define ROWS 16384
#define NCHUNK 64

#if defined(__CUDA_ARCH__) && (defined(__CUDA_ARCH_FEAT_SM103_ALL) || defined(__CUDA_ARCH_FEAT_SM100_ALL) || defined(__CUDA_ARCH_FEAT_SM101_ALL))
#define HAS_TC 1
#else
#define HAS_TC 0
#endif

// ---- static scratch (no allocations) ----
__device__ __align__(1024) unsigned char g_w2img[NCHUNK * 32768]; // w_w2 chunks: 64 x (64r x 256c bf16)
__device__ __align__(1024) unsigned char g_w1img[65536];          // w_w1: 256x128 bf16 image
__device__ __align__(1024) unsigned char g_bw1img[65536];         // b_w1: 256x128
__device__ __align__(1024) unsigned char g_bw2img[32768];         // b_w2: 64x256

// ---- helpers usable on all targets ----
__device__ __forceinline__ uint32_t swz(uint32_t b) { return b ^ ((b >> 3) & 0x70); }
__device__ __forceinline__ uint32_t imgoff(int row, int col, int natoms) {
    return (uint32_t)(((row >> 3) + (col >> 6) * natoms) * 1024 + (row & 7) * 128 + (col & 63) * 2);
}
__device__ __forceinline__ uint32_t packbf(float lo, float hi) {
    uint32_t r; asm("cvt.rn.bf16x2.f32 %0, %1, %2;" : "=r"(r) : "f"(hi), "f"(lo)); return r;
}
__device__ __forceinline__ float tanh_ap(float x) { float y; asm("tanh.approx.f32 %0, %1;" : "=f"(y) : "f"(x)); return y; }

// ================= P0: build bf16 weight images =================
__global__ void p0(const float* __restrict__ w_w1, const float* __restrict__ w_w2,
                   const float* __restrict__ b_w1, const float* __restrict__ b_w2)
{
    const int t = blockIdx.x * blockDim.x + threadIdx.x;
    const int NT = gridDim.x * blockDim.x;
    for (int p = t; p < NCHUNK * 64 * 128; p += NT) {           // w_w2 chunks (natoms=8)
        int ch = p >> 13, rem = p & 8191, row = rem >> 7, col = (rem & 127) * 2;
        int n = ch * 64 + row;
        *(uint32_t*)&g_w2img[ch * 32768u + swz(imgoff(row, col, 8))] =
            packbf(w_w2[n * 256 + col], w_w2[n * 256 + col + 1]);
    }
    for (int p = t; p < 256 * 64; p += NT) {                    // w_w1 / b_w1 (natoms=32)
        int row = p >> 6, col = (p & 63) * 2;
        uint32_t off = swz(imgoff(row, col, 32));
        *(uint32_t*)&g_w1img[off]  = packbf(w_w1[row * 128 + col], w_w1[row * 128 + col + 1]);
        *(uint32_t*)&g_bw1img[off] = packbf(b_w1[row * 128 + col], b_w1[row * 128 + col + 1]);
    }
    for (int p = t; p < 64 * 128; p += NT) {                    // b_w2 (natoms=8)
        int row = p >> 7, col = (p & 127) * 2;
        *(uint32_t*)&g_bw2img[swz(imgoff(row, col, 8))] =
            packbf(b_w2[row * 256 + col], b_w2[row * 256 + col + 1]);
    }
}

#if HAS_TC
// ---- tcgen05-only helpers ----
__device__ __forceinline__ uint32_t s2u(const void* p) {
    uint32_t a; asm("{ .reg .u64 t; cvta.to.shared.u64 t, %1; cvt.u32.u64 %0, t; }" : "=r"(a) : "l"(p)); return a;
}
__device__ __forceinline__ uint32_t elect1() {
    uint32_t p; asm volatile("{\n\t.reg .pred p;\n\telect.sync _|p, 0xFFFFFFFF;\n\tselp.b32 %0,1,0,p;\n\t}" : "=r"(p)); return p;
}
__device__ __forceinline__ uint64_t mkdesc(uint32_t a) {
    return ((uint64_t)2 << 61) | ((uint64_t)1 << 46) | ((uint64_t)64 << 32) | ((uint64_t)1 << 16) | ((uint64_t)(a >> 4) & 0x3FFF);
}
__device__ __forceinline__ void mma_ss(uint32_t d, uint64_t ad, uint64_t bd, uint32_t idesc, uint32_t en) {
    asm volatile("{\n\t.reg .pred p;\n\tsetp.ne.u32 p, %5, 0;\n\t"
        "tcgen05.mma.cta_group::1.kind::f16 [%0], %1, %2, %3, {%4,%4,%4,%4}, p;\n\t}"
        :: "r"(d), "l"(ad), "l"(bd), "r"(idesc), "r"(0u), "r"(en) : "memory");
}
__device__ __forceinline__ void issue_gemm(uint32_t d, uint64_t ad, uint64_t bd, int nks,
                                           uint32_t astr, uint32_t bstr, uint32_t idesc) {
    for (int ks = 0; ks < nks; ++ks)
        mma_ss(d, ad + (ks & 3) * 2 + (ks >> 2) * astr, bd + (ks & 3) * 2 + (ks >> 2) * bstr, idesc, ks > 0);
}
__device__ __forceinline__ void bulk_ld(uint32_t dst, const void* src, uint32_t bytes, uint32_t mbar) {
    uint64_t g; asm("cvta.to.global.u64 %0, %1;" : "=l"(g) : "l"(src));
    asm volatile("mbarrier.arrive.expect_tx.shared.b64 _, [%0], %1;" :: "r"(mbar), "r"(bytes) : "memory");
    asm volatile("cp.async.bulk.shared::cta.global.mbarrier::complete_tx::bytes [%0], [%1], %2, [%3];"
                 :: "r"(dst), "l"(g), "r"(bytes), "r"(mbar) : "memory");
}
#define TC_COMMIT(mb) asm volatile("tcgen05.commit.cta_group::1.mbarrier::arrive::one.shared::cluster.b64 [%0];" :: "r"(mb) : "memory")
#define TC_WAIT_LD()  asm volatile("tcgen05.wait::ld.sync.aligned;" ::: "memory")
#define TC_FA()       asm volatile("tcgen05.fence::after_thread_sync;" ::: "memory")
#define TC_FB()       asm volatile("tcgen05.fence::before_thread_sync;" ::: "memory")
#define FPROXY()      asm volatile("fence.proxy.async.shared::cta;" ::: "memory")
#define MBAR_INIT(mb, n) asm volatile("mbarrier.init.shared.b64 [%0], %1;" :: "r"(mb), "r"(n) : "memory")
#define MBAR_ARRIVE(mb)  asm volatile("mbarrier.arrive.shared.b64 _, [%0];" :: "r"(mb) : "memory")
#define MBAR_WAIT(mb, par) do {                                                        \
    uint32_t _m = (mb), _p = (par), _d;                                                \
    asm volatile("{\n\t.reg .pred p;\n\t"                                              \
      "mbarrier.try_wait.parity.acquire.cta.shared::cta.b64 p, [%1], %2;\n\t"          \
      "selp.b32 %0,1,0,p;\n\t}" : "=r"(_d) : "r"(_m), "r"(_p) : "memory");             \
    if (!_d) { asm volatile("{\n\t.reg .pred P1;\n\tWL_%=:\n\t"                        \
      "mbarrier.try_wait.parity.acquire.cta.shared::cta.b64 P1, [%0], %1, 0x989680;\n\t" \
      "@P1 bra.uni WD_%=;\n\tbra.uni WL_%=;\n\tWD_%=:\n\t}" :: "r"(_m), "r"(_p) : "memory"); } \
} while (0)
#define LDTM32(r, a)                                                                   \
    asm volatile("tcgen05.ld.sync.aligned.32x32b.x32.b32 "                             \
      "{%0,%1,%2,%3,%4,%5,%6,%7,%8,%9,%10,%11,%12,%13,%14,%15,"                        \
      "%16,%17,%18,%19,%20,%21,%22,%23,%24,%25,%26,%27,%28,%29,%30,%31}, [%32];"       \
      : "=r"((r)[0]),"=r"((r)[1]),"=r"((r)[2]),"=r"((r)[3]),"=r"((r)[4]),"=r"((r)[5]), \
        "=r"((r)[6]),"=r"((r)[7]),"=r"((r)[8]),"=r"((r)[9]),"=r"((r)[10]),"=r"((r)[11]),\
        "=r"((r)[12]),"=r"((r)[13]),"=r"((r)[14]),"=r"((r)[15]),"=r"((r)[16]),"=r"((r)[17]),\
        "=r"((r)[18]),"=r"((r)[19]),"=r"((r)[20]),"=r"((r)[21]),"=r"((r)[22]),"=r"((r)[23]),\
        "=r"((r)[24]),"=r"((r)[25]),"=r"((r)[26]),"=r"((r)[27]),"=r"((r)[28]),"=r"((r)[29]),\
        "=r"((r)[30]),"=r"((r)[31]) : "r"(a))

#define IDESC_N64  0x8100490u
#define IDESC_N256 0x8400490u
#endif // HAS_TC

// smem map (bytes), all bases 1024-aligned
#define SM_HW    1024u     // w_w1 image (prologue) -> h_w A-image (loop), 64K
#define SM_RING0 66560u    // emb image (prologue) / b_w2 image (prologue) -> B ring buf0, 32K
#define SM_RING1 99328u    // b_w1 image low half... b_w1 image occupies [99328,164864) prologue -> B ring buf1, 32K
#define SM_SIN   132096u   // h_b image (prologue, 64K) -> input-T 64x128 f32 (32K)
#define SM_SELJ  164864u   // ...        -> exp(logj)-T 64x128 f32 (32K)
#define SM_WB2   197632u   // w_b2 copy, 16K
#define SM_TOT   214016u

// ================= main fused kernel =================
__global__ __launch_bounds__(256, 1)
void bnaf_tc(const float* __restrict__ g_input, const float* __restrict__ g_wemb,
             const float* __restrict__ g_logj,
             const float* __restrict__ w_w1, const float* __restrict__ w_b1,
             const float* __restrict__ w_w2, const float* __restrict__ w_b2,
             const float* __restrict__ b_w1, const float* __restrict__ b_b1,
             const float* __restrict__ b_w2, const float* __restrict__ b_b2,
             float* __restrict__ g_out)
{
#if HAS_TC
    extern __shared__ __align__(1024) unsigned char sm[];
    const uint32_t sb = s2u(sm);
    const int tid = threadIdx.x, wid = tid >> 5, lane = tid & 31;
    const int rowid = (wid & 3) * 32 + lane;          // owned D row
    const int cbase = (wid >> 2) * 32;                // owned col half
    const size_t rbase = (size_t)blockIdx.x * 128;
    const uint32_t mbh = sb + 16;
    const uint32_t mb_bfull[2] = { sb + 24, sb + 32 };
    const uint32_t mb_mdone[2] = { sb + 40, sb + 48 };
    const uint32_t mb_dref [2] = { sb + 56, sb + 64 };

    if (wid == 0) asm volatile("tcgen05.alloc.cta_group::1.sync.aligned.shared::cta.b32 [%0], 512;" :: "r"(sb) : "memory");
    if (tid == 0) {
        MBAR_INIT(mbh, 1);
        MBAR_INIT(mb_bfull[0], 1); MBAR_INIT(mb_bfull[1], 1);
        MBAR_INIT(mb_mdone[0], 1); MBAR_INIT(mb_mdone[1], 1);
        MBAR_INIT(mb_dref[0], 8);  MBAR_INIT(mb_dref[1], 8);
    }

    // ---------- prologue: hypernets ----------
    // emb A-image (M=128,K=128,natoms=16) at SM_RING0
    for (int p = tid; p < 128 * 64; p += 256) {
        int row = p >> 6, col = (p & 63) * 2;
        float2 v = *(const float2*)&g_wemb[(rbase + row) * 128 + col];
        *(uint32_t*)&sm[SM_RING0 + swz(imgoff(row, col, 16))] = packbf(v.x, v.y);
    }
    // w_w1 image -> SM_HW ; b_w1 image -> SM_RING1 (occupies 64K up into SM_SIN area, freed later)
    { const uint4* s = (const uint4*)g_w1img;  uint4* d = (uint4*)(sm + SM_HW);
      for (int j = tid; j < 4096; j += 256) d[j] = s[j]; }
    { const uint4* s = (const uint4*)g_bw1img; uint4* d = (uint4*)(sm + SM_RING1);
      for (int j = tid; j < 4096; j += 256) d[j] = s[j]; }
    FPROXY(); __syncthreads();
    const uint32_t tb = *(const uint32_t*)&sm[0];

    // both hypernet MMAs, one commit: h_w preact -> D[256..511], h_b preact -> D[0..255]
    if (wid == 0 && elect1()) {
        issue_gemm(tb + 256, mkdesc(sb + SM_RING0), mkdesc(sb + SM_HW),    8, 1024, 2048, IDESC_N256);
        issue_gemm(tb + 0,   mkdesc(sb + SM_RING0), mkdesc(sb + SM_RING1), 8, 1024, 2048, IDESC_N256);
        TC_COMMIT(mbh);
    }
    MBAR_WAIT(mbh, 0); TC_FA();

    // h_b: tanh(pre + b_b1) -> bf16 A-image at SM_SIN..(64K) (natoms=16)
    {
        const int chalf = (wid >> 2) * 128;
        for (int j = 0; j < 4; ++j) {
            uint32_t r[32]; LDTM32(r, tb + 0 + chalf + j * 32); TC_WAIT_LD();
            const int cb = chalf + j * 32;
            #pragma unroll
            for (int c = 0; c < 32; c += 2) {
                float a0 = __uint_as_float(r[c])     + __ldg(b_b1 + cb + c);
                float a1 = __uint_as_float(r[c + 1]) + __ldg(b_b1 + cb + c + 1);
                *(uint32_t*)&sm[SM_SIN + swz(imgoff(rowid, cb + c, 16))] = packbf(tanh_ap(a0), tanh_ap(a1));
            }
        }
    }
    // b_w2 image -> SM_RING0 (emb dead after hypernet MMAs)
    { const uint4* s = (const uint4*)g_bw2img; uint4* d = (uint4*)(sm + SM_RING0);
      for (int j = tid; j < 2048; j += 256) d[j] = s[j]; }
    TC_FB(); FPROXY(); __syncthreads();
    // b1 MMA -> D[0..63]
    if (wid == 0 && elect1()) {
        TC_FA();
        issue_gemm(tb + 0, mkdesc(sb + SM_SIN), mkdesc(sb + SM_RING0), 16, 1024, 512, IDESC_N64);
        TC_COMMIT(mbh);
    }
    MBAR_WAIT(mbh, 1); TC_FA();

    float outA[32], lsum[32];
    {   // read b1, init accumulators
        uint32_t r[32]; LDTM32(r, tb + 0 + cbase); TC_WAIT_LD();
        #pragma unroll
        for (int c = 0; c < 32; ++c) { outA[c] = __uint_as_float(r[c]) + __ldg(b_b2 + cbase + c); lsum[c] = 0.f; }
    }
    // h_w: tanh(pre + w_b1) -> A-image at SM_HW (w_w1 dead)
    {
        const int chalf = (wid >> 2) * 128;
        for (int j = 0; j < 4; ++j) {
            uint32_t r[32]; LDTM32(r, tb + 256 + chalf + j * 32); TC_WAIT_LD();
            const int cb = chalf + j * 32;
            #pragma unroll
            for (int c = 0; c < 32; c += 2) {
                float a0 = __uint_as_float(r[c])     + __ldg(w_b1 + cb + c);
                float a1 = __uint_as_float(r[c + 1]) + __ldg(w_b1 + cb + c + 1);
                *(uint32_t*)&sm[SM_HW + swz(imgoff(rowid, cb + c, 16))] = packbf(tanh_ap(a0), tanh_ap(a1));
            }
        }
    }
    __syncthreads();   // h_b image / b_w2 reads done; SM_SIN & ring now reusable

    // stage epilogue data + B chunks 0,1
    {
        float* s_in  = (float*)(sm + SM_SIN);
        float* s_elj = (float*)(sm + SM_SELJ);
        for (int p = tid; p < 8192; p += 256) {
            int row = p >> 6, col = p & 63;
            s_in [col * 128 + row] = g_input[(rbase + row) * 64 + col];
            s_elj[col * 128 + row] = __expf(g_logj[(rbase + row) * 64 + col]);
        }
        float* s_wb2 = (float*)(sm + SM_WB2);
        for (int p = tid; p < 4096; p += 256) s_wb2[p] = w_b2[p];
        uint4* d0 = (uint4*)(sm + SM_RING0);
        uint4* d1 = (uint4*)(sm + SM_RING1);
        const uint4* s0 = (const uint4*)(g_w2img);
        const uint4* s1 = (const uint4*)(g_w2img + 32768);
        for (int j = tid; j < 2048; j += 256) { d0[j] = s0[j]; d1[j] = s1[j]; }
    }
    TC_FB(); FPROXY(); __syncthreads();

    const uint64_t hwdesc = mkdesc(sb + SM_HW);
    if (wid == 0 && elect1()) {
        TC_FA();
        issue_gemm(tb + 0, hwdesc, mkdesc(sb + SM_RING0), 16, 1024, 512, IDESC_N64);
        TC_COMMIT(mb_mdone[0]);
    }

    const float* s_in  = (const float*)(sm + SM_SIN);
    const float* s_elj = (const float*)(sm + SM_SELJ);

    // ---------- main loop: no __syncthreads, mbarrier pipeline ----------
    #pragma unroll 1
    for (int i = 0; i < NCHUNK; ++i) {
        MBAR_WAIT(mb_mdone[i & 1], (i >> 1) & 1);     // MMA(i) complete
        if (wid == 0 && elect1()) {
            // buffer (i&1) is free (MMA(i) done) -> fetch chunk i+2
            if (i + 2 < NCHUNK)
                bulk_ld(sb + SM_RING0 + (uint32_t)(i & 1) * 32768u,
                        g_w2img + (size_t)(i + 2) * 32768u, 32768u, mb_bfull[i & 1]);
            // issue MMA(i+1): needs chunk i+1 staged, and D[(i+1)&1] readers (iter i-1) done
            if (i + 1 < NCHUNK) {
                const int j = i + 1;
                if (j >= 2) MBAR_WAIT(mb_bfull[j & 1], ((j >> 1) - 1) & 1);
                if (i >= 1) MBAR_WAIT(mb_dref[j & 1], ((i - 1) >> 1) & 1);
                issue_gemm(tb + (j & 1) * 64, hwdesc, mkdesc(sb + SM_RING0 + (uint32_t)(j & 1) * 32768u),
                           16, 1024, 512, IDESC_N64);
                TC_COMMIT(mb_mdone[j & 1]);
            }
        }
        TC_FA();
        uint32_t r[32];
        LDTM32(r, tb + (i & 1) * 64 + cbase);
        TC_WAIT_LD();
        TC_FB();
        if (elect1()) MBAR_ARRIVE(mb_dref[i & 1]);    // this warp done reading D[i&1]
        // epilogue
        const float inp = s_in [i * 128 + rowid];
        const float el  = s_elj[i * 128 + rowid];
        const float4* wb = (const float4*)(sm + SM_WB2 + (uint32_t)i * 256u + (uint32_t)cbase * 4u);
        #pragma unroll
        for (int q = 0; q < 8; ++q) {
            const float4 b = wb[q];
            const int c = q * 4;
            float e0 = __expf(__uint_as_float(r[c + 0]) + b.x);
            float e1 = __expf(__uint_as_float(r[c + 1]) + b.y);
            float e2 = __expf(__uint_as_float(r[c + 2]) + b.z);
            float e3 = __expf(__uint_as_float(r[c + 3]) + b.w);
            outA[c + 0] = fmaf(inp, e0, outA[c + 0]); lsum[c + 0] = fmaf(el, e0, lsum[c + 0]);
            outA[c + 1] = fmaf(inp, e1, outA[c + 1]); lsum[c + 1] = fmaf(el, e1, lsum[c + 1]);
            outA[c + 2] = fmaf(inp, e2, outA[c + 2]); lsum[c + 2] = fmaf(el, e2, lsum[c + 2]);
            outA[c + 3] = fmaf(inp, e3, outA[c + 3]); lsum[c + 3] = fmaf(el, e3, lsum[c + 3]);
        }
    }

    // ---------- store ----------
    {
        const size_t go = (rbase + rowid) * 64 + cbase;
        #pragma unroll
        for (int c = 0; c < 32; c += 4) {
            float4 v; v.x = outA[c]; v.y = outA[c + 1]; v.z = outA[c + 2]; v.w = outA[c + 3];
            *(float4*)&g_out[go + c] = v;
            float4 w; w.x = __logf(lsum[c]); w.y = __logf(lsum[c + 1]);
            w.z = __logf(lsum[c + 2]); w.w = __logf(lsum[c + 3]);
            *(float4*)&g_out[(size_t)ROWS * 64 + go + c] = w;
        }
    }
    __syncthreads();
    if (wid == 0) {
        asm volatile("tcgen05.relinquish_alloc_permit.cta_group::1.sync.aligned;");
        asm volatile("tcgen05.dealloc.cta_group::1.sync.aligned.b32 %0, 512;" :: "r"(tb));
    }

#else  // ===================== SIMT fallback (non-'a' targets) =====================
    extern __shared__ __align__(1024) unsigned char smraw[];
    float* fsm = (float*)smraw;
    float* sh_h   = fsm;
    float* sh_emb = sh_h   + 64 * 256;
    float* sh_B   = sh_emb + 64 * 128;
    float* sh_in  = sh_B   + 64 * 68;
    float* sh_lj  = sh_in  + 64 * 64;
    float* sh_wb2 = sh_lj  + 64 * 64;
    const int tid = threadIdx.x;
    const int r0 = ((tid >> 4) << 2);
    const int o0 = ((tid & 15) << 2);

    for (int half = 0; half < 2; ++half) {
        const size_t rbase = (size_t)blockIdx.x * 128 + half * 64;
        for (int p = tid; p < 64 * 128; p += 256) sh_emb[p] = g_wemb[rbase * 128 + p];
        for (int p = tid; p < 64 * 64;  p += 256) { sh_in[p] = g_input[rbase * 64 + p]; sh_lj[p] = g_logj[rbase * 64 + p]; }
        for (int p = tid; p < 4096;     p += 256) sh_wb2[p] = w_b2[p];
        __syncthreads();

        float outA[16], mA[16], sA[16];
        {
            const float bias = b_b1[tid];
            for (int rc = 0; rc < 4; ++rc) {
                float acc[16];
                #pragma unroll
                for (int rr = 0; rr < 16; ++rr) acc[rr] = bias;
                for (int k = 0; k < 128; k += 4) {
                    const float4 wv = *(const float4*)(b_w1 + tid * 128 + k);
                    #pragma unroll
                    for (int rr = 0; rr < 16; ++rr) {
                        const float4 ev = *(const float4*)&sh_emb[(rc * 16 + rr) * 128 + k];
                        acc[rr] = fmaf(ev.x, wv.x, fmaf(ev.y, wv.y, fmaf(ev.z, wv.z, fmaf(ev.w, wv.w, acc[rr]))));
                    }
                }
                #pragma unroll
                for (int rr = 0; rr < 16; ++rr) sh_h[(rc * 16 + rr) * 256 + tid] = tanhf(acc[rr]);
            }
        }
        __syncthreads();
        {
            float acc[16];
            #pragma unroll
            for (int c = 0; c < 16; ++c) acc[c] = 0.f;
            for (int k = 0; k < 256; k += 4) {
                float4 a[4], b[4];
                #pragma unroll
                for (int ri = 0; ri < 4; ++ri) a[ri] = *(const float4*)&sh_h[(r0 + ri) * 256 + k];
                #pragma unroll
                for (int oi = 0; oi < 4; ++oi) b[oi] = *(const float4*)(b_w2 + (o0 + oi) * 256 + k);
                #pragma unroll
                for (int ri = 0; ri < 4; ++ri)
                    #pragma unroll
                    for (int oi = 0; oi < 4; ++oi) {
                        int c = ri * 4 + oi;
                        acc[c] = fmaf(a[ri].x, b[oi].x, fmaf(a[ri].y, b[oi].y, fmaf(a[ri].z, b[oi].z, fmaf(a[ri].w, b[oi].w, acc[c]))));
                    }
            }
            #pragma unroll
            for (int ri = 0; ri < 4; ++ri)
                #pragma unroll
                for (int oi = 0; oi < 4; ++oi) {
                    int c = ri * 4 + oi;
                    outA[c] = acc[c] + b_b2[o0 + oi];
                    mA[c] = -__int_as_float(0x7f800000); sA[c] = 0.f;
                }
        }
        __syncthreads();
        {
            const float bias = w_b1[tid];
            for (int rc = 0; rc < 4; ++rc) {
                float acc[16];
                #pragma unroll
                for (int rr = 0; rr < 16; ++rr) acc[rr] = bias;
                for (int k = 0; k < 128; k += 4) {
                    const float4 wv = *(const float4*)(w_w1 + tid * 128 + k);
                    #pragma unroll
                    for (int rr = 0; rr < 16; ++rr) {
                        const float4 ev = *(const float4*)&sh_emb[(rc * 16 + rr) * 128 + k];
                        acc[rr] = fmaf(ev.x, wv.x, fmaf(ev.y, wv.y, fmaf(ev.z, wv.z, fmaf(ev.w, wv.w, acc[rr]))));
                    }
                }
                #pragma unroll
                for (int rr = 0; rr < 16; ++rr) sh_h[(rc * 16 + rr) * 256 + tid] = tanhf(acc[rr]);
            }
        }
        __syncthreads();

        for (int i = 0; i < 64; ++i) {
            float w1a[16];
            #pragma unroll
            for (int c = 0; c < 16; ++c) w1a[c] = 0.f;
            const float4* gB = (const float4*)(w_w2 + (size_t)i * 64 * 256);
            for (int kc = 0; kc < 4; ++kc) {
                #pragma unroll
                for (int st = 0; st < 4; ++st) {
                    int idx = tid + st * 256;
                    int row = idx >> 4, c4 = idx & 15;
                    *(float4*)&sh_B[row * 68 + c4 * 4] = gB[row * 64 + kc * 16 + c4];
                }
                __syncthreads();
                const float* hrow = sh_h + kc * 64;
                for (int kk = 0; kk < 64; kk += 4) {
                    float4 a[4], b[4];
                    #pragma unroll
                    for (int ri = 0; ri < 4; ++ri) a[ri] = *(const float4*)&hrow[(r0 + ri) * 256 + kk];
                    #pragma unroll
                    for (int oi = 0; oi < 4; ++oi) b[oi] = *(const float4*)&sh_B[(o0 + oi) * 68 + kk];
                    #pragma unroll
                    for (int ri = 0; ri < 4; ++ri)
                        #pragma unroll
                        for (int oi = 0; oi < 4; ++oi) {
                            int c = ri * 4 + oi;
                            w1a[c] = fmaf(a[ri].x, b[oi].x, fmaf(a[ri].y, b[oi].y, fmaf(a[ri].z, b[oi].z, fmaf(a[ri].w, b[oi].w, w1a[c]))));
                        }
                }
                __syncthreads();
            }
            #pragma unroll
            for (int ri = 0; ri < 4; ++ri) {
                const float inp = sh_in[(r0 + ri) * 64 + i];
                const float lj  = sh_lj[(r0 + ri) * 64 + i];
                #pragma unroll
                for (int oi = 0; oi < 4; ++oi) {
                    const int c = ri * 4 + oi;
                    const float w1 = w1a[c] + sh_wb2[i * 64 + o0 + oi];
                    outA[c] = fmaf(inp, __expf(w1), outA[c]);
                    const float z = w1 + lj;
                    const float mn = fmaxf(mA[c], z);
                    sA[c] = sA[c] * __expf(mA[c] - mn) + __expf(z - mn);
                    mA[c] = mn;
                }
            }
        }
        #pragma unroll
        for (int ri = 0; ri < 4; ++ri) {
            const size_t row = rbase + r0 + ri;
            float4 ov, lv;
            ov.x = outA[ri*4+0]; ov.y = outA[ri*4+1]; ov.z = outA[ri*4+2]; ov.w = outA[ri*4+3];
            lv.x = mA[ri*4+0] + logf(sA[ri*4+0]); lv.y = mA[ri*4+1] + logf(sA[ri*4+1]);
            lv.z = mA[ri*4+2] + logf(sA[ri*4+2]); lv.w = mA[ri*4+3] + logf(sA[ri*4+3]);
            *(float4*)&g_out[row * 64 + o0] = ov;
            *(float4*)&g_out[(size_t)ROWS * 64 + row * 64 + o0] = lv;
        }
        __syncthreads();
    }
#endif
}

extern "C" void kernel_launch(void* const* d_in, const int* in_sizes, int n_in,
                              void* d_out, int out_size)
{
    const float* input = (const float*)d_in[0];
    const float* wemb  = (const float*)d_in[1];
    const float* logj  = (const float*)d_in[2];
    const float* w_w1  = (const float*)d_in[3];
    const float* w_b1  = (const float*)d_in[4];
    const float* w_w2  = (const float*)d_in[5];
    const float* w_b2  = (const float*)d_in[6];
    const float* b_w1  = (const float*)d_in[7];
    const float* b_b1  = (const float*)d_in[8];
    const float* b_w2  = (const float*)d_in[9];
    const float* b_b2  = (const float*)d_in[10];

    p0<<<256, 256>>>(w_w1, w_w2, b_w1, b_w2);
    cudaFuncSetAttribute(bnaf_tc, cudaFuncAttributeMaxDynamicSharedMemorySize, SM_TOT);
    bnaf_tc<<<128, 256, SM_TOT>>>(input, wemb, logj,
                                  w_w1, w_b1, w_w2, w_b2,
                                  b_w1, b_b1, b_w2, b_b2, (float*)d_out);
}